// round 5
// baseline (speedup 1.0000x reference)
#include <cuda_runtime.h>
#include <cstdint>

// Problem constants
static constexpr int Lc  = 32;
static constexpr int Kc  = 4;
static constexpr int Dc  = 1024;
static constexpr int QOc = 1024;
static constexpr int KVc = 256;
static constexpr int FFc = 2816;

static constexpr int S        = 256;      // stage width (floats)
static constexpr int ROWS_BLK = 16;       // d-rows per block
static constexpr int RW       = 8;        // rows per warp
static constexpr int CSLOT_F  = 12 * S;   // cursed slot (max M), floats

typedef unsigned long long ull;

// ---------------- f32x2 packed FMA (sm_103a) ----------------
__device__ __forceinline__ void ffma2(ull& acc, ull a, ull b) {
    asm("fma.rn.f32x2 %0, %1, %2, %0;" : "+l"(acc) : "l"(a), "l"(b));
}
__device__ __forceinline__ float hsum2(ull v) {
    return __uint_as_float((uint32_t)v) + __uint_as_float((uint32_t)(v >> 32));
}

// ---------------- cp.async helpers ----------------
__device__ __forceinline__ void cp_async16(uint32_t saddr, const void* gptr) {
    asm volatile("cp.async.cg.shared.global [%0], [%1], 16;" :: "r"(saddr), "l"(gptr));
}
__device__ __forceinline__ void cp_commit() {
    asm volatile("cp.async.commit_group;");
}
template<int N>
__device__ __forceinline__ void cp_wait() {
    asm volatile("cp.async.wait_group %0;" :: "n"(N));
}

// Stage M x S floats of cursed data (cols [c0,c0+S)) into smem slot. 256 thr.
template<int M, int I>
__device__ __forceinline__ void stage_cursed(uint32_t sbuf, const float* __restrict__ Cl,
                                             int c0, int tid)
{
#pragma unroll
    for (int idx = tid; idx < M * (S / 4); idx += 256) {
        const int j   = idx >> 6;         // S/4 = 64 transfers per vec
        const int c16 = idx & 63;
        cp_async16(sbuf + (uint32_t)(j * S + c16 * 4) * 4u,
                   Cl + (size_t)j * I + c0 + c16 * 4);
    }
}

// ---------------- projection tile ----------------
// Block: 256 threads = 8 warps = 2 row-groups(8 rows) x 4 M-groups(M/4 vecs).
// Weights: direct cached LDG (row read by 4 warps -> 1 DRAM + 3 L1 hits).
// Cursed: cp.async 3-slot ring, each warp reads only its M/4 vecs.
template<int M, int I, bool IS_MLP, int MFIX>
__device__ __forceinline__ void proj_tile(
    const float* __restrict__ Wl,   // layer weight [D][I]
    const float* __restrict__ Cl,   // layer cursed vecs [M][I]
    float* __restrict__ out,
    float* __restrict__ smem,       // [3][CSLOT_F]
    int l, int d0)
{
    constexpr int MG = M / 4;       // vecs per warp
    const int tid   = threadIdx.x;
    const int lane  = tid & 31;
    const int warp  = tid >> 5;
    const int rg    = warp >> 2;    // row-group 0/1
    const int g     = warp & 3;     // M-group 0..3
    const int dbase = d0 + rg * RW;
    const uint32_t smem_u32 = (uint32_t)__cvta_generic_to_shared(smem);
    constexpr int NS = I / S;
    constexpr uint32_t SLOTB = (uint32_t)(CSLOT_F * 4);

    ull acc2[RW][MG];
#pragma unroll
    for (int t = 0; t < RW; ++t)
#pragma unroll
        for (int j = 0; j < MG; ++j) acc2[t][j] = 0ull;

    const float* wrow = Wl + (size_t)dbase * I;   // this warp's 8 rows

    // Prime 3-slot ring
    stage_cursed<M, I>(smem_u32, Cl, 0, tid);
    cp_commit();
    if (NS > 1) {
        stage_cursed<M, I>(smem_u32 + SLOTB, Cl, S, tid);
        cp_commit();
    }

    for (int s = 0; s < NS; ++s) {
        if (s == NS - 1) cp_wait<0>(); else cp_wait<1>();
        __syncthreads();

        const float* cbuf = smem + (s % 3) * CSLOT_F + (g * MG) * S;
        const int c0 = s * S;

#pragma unroll
        for (int u = 0; u < 2; ++u) {
            // 8 weight rows, 16B per lane, cached in L1 (reused by 4 warps)
            ull w01[RW], w23[RW];
#pragma unroll
            for (int t = 0; t < RW; ++t) {
                const double2 wd = *reinterpret_cast<const double2*>(
                    wrow + (size_t)t * I + c0 + u * 128 + lane * 4);
                w01[t] = __double_as_longlong(wd.x);
                w23[t] = __double_as_longlong(wd.y);
            }
#pragma unroll
            for (int j = 0; j < MG; ++j) {
                const double2 cd = *reinterpret_cast<const double2*>(
                    cbuf + j * S + u * 128 + lane * 4);
                const ull c01 = __double_as_longlong(cd.x);
                const ull c23 = __double_as_longlong(cd.y);
#pragma unroll
                for (int t = 0; t < RW; ++t) {
                    ffma2(acc2[t][j], w01[t], c01);
                    ffma2(acc2[t][j], w23[t], c23);
                }
            }
        }

        // Prefetch stage s+2 into slot (s+2)%3: its last readers (stage s-1)
        // finished before the barrier all threads passed this stage.
        if (s + 2 < NS) {
            stage_cursed<M, I>(smem_u32 + (uint32_t)((s + 2) % 3) * SLOTB,
                               Cl, (s + 2) * S, tid);
            cp_commit();
        }
    }

    // Fold f32x2 pairs, butterfly-reduce across lanes, scatter stores.
#pragma unroll
    for (int t = 0; t < RW; ++t)
#pragma unroll
        for (int j = 0; j < MG; ++j) {
            float v = hsum2(acc2[t][j]);
            v += __shfl_xor_sync(0xffffffffu, v, 16);
            v += __shfl_xor_sync(0xffffffffu, v, 8);
            v += __shfl_xor_sync(0xffffffffu, v, 4);
            v += __shfl_xor_sync(0xffffffffu, v, 2);
            v += __shfl_xor_sync(0xffffffffu, v, 1);
            if (lane == t * MG + j) {
                const int jj = g * MG + j;        // global vec index
                int m, k;
                if (IS_MLP) {
                    const int mi = jj >> 2;        // 0,1,2 -> gate, up, down
                    m = (mi == 2) ? 6 : (3 + mi);  // gate=3, up=4, down=6
                    k = jj & 3;
                } else {
                    m = MFIX;
                    k = jj;
                }
                const size_t row = ((size_t)(l * 7 + m) * 2 + 1) * Kc + k;
                out[row * Dc + (size_t)(dbase + t)] = v;
            }
        }
}

// Block segments (16 d-rows per proj block, 2048 blocks per matrix):
//   [0,2048) mlp  [2048,4096) q  [4096,6144) o  [6144,8192) k
//   [8192,10240) v  [10240,10496) residual copy
extern "C" __global__ void __launch_bounds__(256, 2)
both_sides_fused(const float* __restrict__ residual,
                 const float* __restrict__ cq, const float* __restrict__ ck,
                 const float* __restrict__ cv, const float* __restrict__ co,
                 const float* __restrict__ cm,
                 const float* __restrict__ Wq, const float* __restrict__ Wk,
                 const float* __restrict__ Wv, const float* __restrict__ Wo,
                 const float* __restrict__ Wd,
                 float* __restrict__ out)
{
    __shared__ __align__(16) float smem[3][CSLOT_F];   // 36 KB

    int b = blockIdx.x;
    if (b < 2048) {                                   // mlp (heaviest first)
        const int l = b >> 6, d0 = (b & 63) * ROWS_BLK;
        proj_tile<12, FFc, true, 0>(Wd + (size_t)l * Dc * FFc,
                                    cm + (size_t)l * 3 * Kc * FFc,
                                    out, &smem[0][0], l, d0);
    } else if (b < 4096) {                            // q (m=0)
        b -= 2048;
        const int l = b >> 6, d0 = (b & 63) * ROWS_BLK;
        proj_tile<4, QOc, false, 0>(Wq + (size_t)l * Dc * QOc,
                                    cq + (size_t)l * Kc * QOc,
                                    out, &smem[0][0], l, d0);
    } else if (b < 6144) {                            // o (m=5)
        b -= 4096;
        const int l = b >> 6, d0 = (b & 63) * ROWS_BLK;
        proj_tile<4, QOc, false, 5>(Wo + (size_t)l * Dc * QOc,
                                    co + (size_t)l * Kc * QOc,
                                    out, &smem[0][0], l, d0);
    } else if (b < 8192) {                            // k (m=1)
        b -= 6144;
        const int l = b >> 6, d0 = (b & 63) * ROWS_BLK;
        proj_tile<4, KVc, false, 1>(Wk + (size_t)l * Dc * KVc,
                                    ck + (size_t)l * Kc * KVc,
                                    out, &smem[0][0], l, d0);
    } else if (b < 10240) {                           // v (m=2)
        b -= 8192;
        const int l = b >> 6, d0 = (b & 63) * ROWS_BLK;
        proj_tile<4, KVc, false, 2>(Wv + (size_t)l * Dc * KVc,
                                    cv + (size_t)l * Kc * KVc,
                                    out, &smem[0][0], l, d0);
    } else {                                          // residual copy (s=0 rows)
        const float4* r4 = reinterpret_cast<const float4*>(residual);
        float4* o4 = reinterpret_cast<float4*>(out);
        const int nf4 = Lc * 7 * Kc * Dc / 4;         // 229376 float4
        for (int i = (b - 10240) * 256 + (int)threadIdx.x; i < nf4; i += 256 * 256) {
            const int chunk  = i >> 10;
            const int within = i & 1023;
            o4[(size_t)chunk * 2048 + within] = r4[i];
        }
    }
}

extern "C" void kernel_launch(void* const* d_in, const int* in_sizes, int n_in,
                              void* d_out, int out_size)
{
    const float* residual = (const float*)d_in[0];
    const float* cq       = (const float*)d_in[1];
    const float* ck       = (const float*)d_in[2];
    const float* cv       = (const float*)d_in[3];
    const float* co       = (const float*)d_in[4];
    const float* cm       = (const float*)d_in[5];
    const float* Wq       = (const float*)d_in[6];
    const float* Wk       = (const float*)d_in[7];
    const float* Wv       = (const float*)d_in[8];
    const float* Wo       = (const float*)d_in[9];
    const float* Wd       = (const float*)d_in[10];
    float* out            = (float*)d_out;

    both_sides_fused<<<10496, 256>>>(residual, cq, ck, cv, co, cm,
                                     Wq, Wk, Wv, Wo, Wd, out);
}

// round 6
// speedup vs baseline: 1.2755x; 1.2755x over previous
#include <cuda_runtime.h>
#include <cstdint>

// Problem constants
static constexpr int Lc  = 32;
static constexpr int Kc  = 4;
static constexpr int Dc  = 1024;
static constexpr int QOc = 1024;
static constexpr int KVc = 256;
static constexpr int FFc = 2816;

static constexpr int S        = 256;      // stage width (floats)
static constexpr int ROWS_BLK = 16;       // d-rows per block
static constexpr int RW       = 4;        // rows per warp (row-group)
static constexpr int CSLOT_F  = 12 * S;   // cursed slot (max M), floats

typedef unsigned long long ull;

// ---------------- f32x2 packed FMA (sm_103a) ----------------
__device__ __forceinline__ void ffma2(ull& acc, ull a, ull b) {
    asm("fma.rn.f32x2 %0, %1, %2, %0;" : "+l"(acc) : "l"(a), "l"(b));
}
__device__ __forceinline__ float hsum2(ull v) {
    return __uint_as_float((uint32_t)v) + __uint_as_float((uint32_t)(v >> 32));
}

// ---------------- cp.async helpers ----------------
__device__ __forceinline__ void cp_async16(uint32_t saddr, const void* gptr) {
    asm volatile("cp.async.cg.shared.global [%0], [%1], 16;" :: "r"(saddr), "l"(gptr));
}
__device__ __forceinline__ void cp_commit() {
    asm volatile("cp.async.commit_group;");
}
template<int N>
__device__ __forceinline__ void cp_wait() {
    asm volatile("cp.async.wait_group %0;" :: "n"(N));
}

// Stage M x S floats of cursed data (cols [c0,c0+S)) into smem slot. 256 thr.
template<int M, int I>
__device__ __forceinline__ void stage_cursed(uint32_t sbuf, const float* __restrict__ Cl,
                                             int c0, int tid)
{
#pragma unroll
    for (int idx = tid; idx < M * (S / 4); idx += 256) {
        const int j   = idx >> 6;         // S/4 = 64 transfers per vec
        const int c16 = idx & 63;
        cp_async16(sbuf + (uint32_t)(j * S + c16 * 4) * 4u,
                   Cl + (size_t)j * I + c0 + c16 * 4);
    }
}

// ---------------- projection tile ----------------
// Block: 256 threads = 8 warps = 4 row-groups(4 rows) x 2 M-groups(M/2 vecs).
// Weights: direct LDG.128 (each row line read by exactly 2 warps: 1 DRAM + 1 L1 hit).
// Cursed: cp.async 3-slot ring; each warp reads only its M/2 vecs from smem.
template<int M, int I, bool IS_MLP, int MFIX>
__device__ __forceinline__ void proj_tile(
    const float* __restrict__ Wl,   // layer weight [D][I]
    const float* __restrict__ Cl,   // layer cursed vecs [M][I]
    float* __restrict__ out,
    float* __restrict__ smem,       // [3][CSLOT_F]
    int l, int d0)
{
    constexpr int MGV = M / 2;      // vecs per warp
    const int tid   = threadIdx.x;
    const int lane  = tid & 31;
    const int warp  = tid >> 5;
    const int rg    = warp >> 1;    // row-group 0..3
    const int g     = warp & 1;     // M-group 0/1
    const int dbase = d0 + rg * RW;
    const uint32_t smem_u32 = (uint32_t)__cvta_generic_to_shared(smem);
    constexpr int NS = I / S;
    constexpr uint32_t SLOTB = (uint32_t)(CSLOT_F * 4);

    ull acc2[RW][MGV];
#pragma unroll
    for (int t = 0; t < RW; ++t)
#pragma unroll
        for (int j = 0; j < MGV; ++j) acc2[t][j] = 0ull;

    const float* wrow = Wl + (size_t)dbase * I;   // this warp's 4 rows

    // Prime 3-slot ring
    stage_cursed<M, I>(smem_u32, Cl, 0, tid);
    cp_commit();
    if (NS > 1) {
        stage_cursed<M, I>(smem_u32 + SLOTB, Cl, S, tid);
        cp_commit();
    }

    for (int s = 0; s < NS; ++s) {
        if (s == NS - 1) cp_wait<0>(); else cp_wait<1>();
        __syncthreads();

        const float* cbuf = smem + (s % 3) * CSLOT_F + (g * MGV) * S;
        const int c0 = s * S;

#pragma unroll
        for (int u = 0; u < 2; ++u) {
            // 4 weight rows, 16B per lane, loaded as double2 (one LDG.128 each)
            ull w01[RW], w23[RW];
#pragma unroll
            for (int t = 0; t < RW; ++t) {
                const double2 wd = *reinterpret_cast<const double2*>(
                    wrow + (size_t)t * I + c0 + u * 128 + lane * 4);
                w01[t] = __double_as_longlong(wd.x);
                w23[t] = __double_as_longlong(wd.y);
            }
#pragma unroll
            for (int j = 0; j < MGV; ++j) {
                const double2 cd = *reinterpret_cast<const double2*>(
                    cbuf + j * S + u * 128 + lane * 4);
                const ull c01 = __double_as_longlong(cd.x);
                const ull c23 = __double_as_longlong(cd.y);
#pragma unroll
                for (int t = 0; t < RW; ++t) {
                    ffma2(acc2[t][j], w01[t], c01);
                    ffma2(acc2[t][j], w23[t], c23);
                }
            }
        }

        // Prefetch stage s+2 into slot (s+2)%3: its previous readers (stage s-1)
        // finished before the barrier every thread passed this stage.
        if (s + 2 < NS) {
            stage_cursed<M, I>(smem_u32 + (uint32_t)((s + 2) % 3) * SLOTB,
                               Cl, (s + 2) * S, tid);
            cp_commit();
        }
    }

    // Fold f32x2 pairs, butterfly-reduce across lanes, scatter stores.
#pragma unroll
    for (int t = 0; t < RW; ++t)
#pragma unroll
        for (int j = 0; j < MGV; ++j) {
            float v = hsum2(acc2[t][j]);
            v += __shfl_xor_sync(0xffffffffu, v, 16);
            v += __shfl_xor_sync(0xffffffffu, v, 8);
            v += __shfl_xor_sync(0xffffffffu, v, 4);
            v += __shfl_xor_sync(0xffffffffu, v, 2);
            v += __shfl_xor_sync(0xffffffffu, v, 1);
            if (lane == t * MGV + j) {
                const int jj = g * MGV + j;       // global vec index
                int m, k;
                if (IS_MLP) {
                    const int mi = jj >> 2;        // 0,1,2 -> gate, up, down
                    m = (mi == 2) ? 6 : (3 + mi);  // gate=3, up=4, down=6
                    k = jj & 3;
                } else {
                    m = MFIX;
                    k = jj;
                }
                const size_t row = ((size_t)(l * 7 + m) * 2 + 1) * Kc + k;
                out[row * Dc + (size_t)(dbase + t)] = v;
            }
        }
}

// Block segments (16 d-rows per proj block, 2048 blocks per matrix):
//   [0,2048) mlp  [2048,4096) q  [4096,6144) o  [6144,8192) k
//   [8192,10240) v  [10240,10496) residual copy
extern "C" __global__ void __launch_bounds__(256, 2)
both_sides_fused(const float* __restrict__ residual,
                 const float* __restrict__ cq, const float* __restrict__ ck,
                 const float* __restrict__ cv, const float* __restrict__ co,
                 const float* __restrict__ cm,
                 const float* __restrict__ Wq, const float* __restrict__ Wk,
                 const float* __restrict__ Wv, const float* __restrict__ Wo,
                 const float* __restrict__ Wd,
                 float* __restrict__ out)
{
    __shared__ __align__(16) float smem[3][CSLOT_F];   // 36 KB

    int b = blockIdx.x;
    if (b < 2048) {                                   // mlp (heaviest first)
        const int l = b >> 6, d0 = (b & 63) * ROWS_BLK;
        proj_tile<12, FFc, true, 0>(Wd + (size_t)l * Dc * FFc,
                                    cm + (size_t)l * 3 * Kc * FFc,
                                    out, &smem[0][0], l, d0);
    } else if (b < 4096) {                            // q (m=0)
        b -= 2048;
        const int l = b >> 6, d0 = (b & 63) * ROWS_BLK;
        proj_tile<4, QOc, false, 0>(Wq + (size_t)l * Dc * QOc,
                                    cq + (size_t)l * Kc * QOc,
                                    out, &smem[0][0], l, d0);
    } else if (b < 6144) {                            // o (m=5)
        b -= 4096;
        const int l = b >> 6, d0 = (b & 63) * ROWS_BLK;
        proj_tile<4, QOc, false, 5>(Wo + (size_t)l * Dc * QOc,
                                    co + (size_t)l * Kc * QOc,
                                    out, &smem[0][0], l, d0);
    } else if (b < 8192) {                            // k (m=1)
        b -= 6144;
        const int l = b >> 6, d0 = (b & 63) * ROWS_BLK;
        proj_tile<4, KVc, false, 1>(Wk + (size_t)l * Dc * KVc,
                                    ck + (size_t)l * Kc * KVc,
                                    out, &smem[0][0], l, d0);
    } else if (b < 10240) {                           // v (m=2)
        b -= 8192;
        const int l = b >> 6, d0 = (b & 63) * ROWS_BLK;
        proj_tile<4, KVc, false, 2>(Wv + (size_t)l * Dc * KVc,
                                    cv + (size_t)l * Kc * KVc,
                                    out, &smem[0][0], l, d0);
    } else {                                          // residual copy (s=0 rows)
        const float4* r4 = reinterpret_cast<const float4*>(residual);
        float4* o4 = reinterpret_cast<float4*>(out);
        const int nf4 = Lc * 7 * Kc * Dc / 4;         // 229376 float4
        for (int i = (b - 10240) * 256 + (int)threadIdx.x; i < nf4; i += 256 * 256) {
            const int chunk  = i >> 10;
            const int within = i & 1023;
            o4[(size_t)chunk * 2048 + within] = r4[i];
        }
    }
}

extern "C" void kernel_launch(void* const* d_in, const int* in_sizes, int n_in,
                              void* d_out, int out_size)
{
    const float* residual = (const float*)d_in[0];
    const float* cq       = (const float*)d_in[1];
    const float* ck       = (const float*)d_in[2];
    const float* cv       = (const float*)d_in[3];
    const float* co       = (const float*)d_in[4];
    const float* cm       = (const float*)d_in[5];
    const float* Wq       = (const float*)d_in[6];
    const float* Wk       = (const float*)d_in[7];
    const float* Wv       = (const float*)d_in[8];
    const float* Wo       = (const float*)d_in[9];
    const float* Wd       = (const float*)d_in[10];
    float* out            = (float*)d_out;

    both_sides_fused<<<10496, 256>>>(residual, cq, ck, cv, co, cm,
                                     Wq, Wk, Wv, Wo, Wd, out);
}